// round 2
// baseline (speedup 1.0000x reference)
#include <cuda_runtime.h>
#include <cstdint>

// Problem constants (fixed shapes per reference)
#define Bn 16
#define Sn 4096
#define Dn 128
#define Ln 8             // timesteps per chunk (small => high occupancy)
#define NCn (Sn / Ln)    // 512 chunks per batch

// -------- scratch (device globals; no allocation allowed) --------
__device__ float g_m [Bn * Sn];          // per-t mean(decay)
__device__ float g_s [Bn * Sn];          // per-t sum(exp(c))
__device__ float g_P [Bn * NCn * Dn];    // chunk decay product per channel
__device__ float g_Q [Bn * NCn * Dn];    // chunk additive term per channel
__device__ float g_AM[Bn * NCn];         // chunk product of m
__device__ float g_AS[Bn * NCn];         // chunk additive term for a
__device__ float g_a0[Bn * NCn];         // a at chunk start (exclusive scan)
__device__ float g_b0[Bn * NCn * Dn];    // bst at chunk start (exclusive scan)

__device__ __forceinline__ float fsig(float x) {
    return __fdividef(1.0f, 1.0f + __expf(-x));
}

__device__ __forceinline__ void warp_allreduce2(float& x, float& y) {
#pragma unroll
    for (int off = 16; off; off >>= 1) {
        x += __shfl_xor_sync(0xffffffffu, x, off);
        y += __shfl_xor_sync(0xffffffffu, y, off);
    }
}

// ============================================================================
// Pass A: per-chunk aggregates. One warp per (batch, chunk); lane owns 4 ch.
// ============================================================================
__global__ void __launch_bounds__(256)
passA_kernel(const float* __restrict__ C, const float* __restrict__ V,
             const float* __restrict__ W, const float* __restrict__ enc,
             const float* __restrict__ tmod, const float* __restrict__ cmod) {
    const int warp = (blockIdx.x * blockDim.x + threadIdx.x) >> 5;
    const int lane = threadIdx.x & 31;
    const int b = warp >> 9;          // / NCn
    const int k = warp & (NCn - 1);
    const int t0 = k * Ln;
    const int d4 = lane * 4;

    const float4 tm = *reinterpret_cast<const float4*>(tmod + d4);
    const float4 cm = *reinterpret_cast<const float4*>(cmod + d4);
    const float4 eb = *reinterpret_cast<const float4*>(enc + b * Dn + d4);
    const float ctx0 = fsig(eb.x * cm.x) * eb.x;
    const float ctx1 = fsig(eb.y * cm.y) * eb.y;
    const float ctx2 = fsig(eb.z * cm.z) * eb.z;
    const float ctx3 = fsig(eb.w * cm.w) * eb.w;

    const size_t base = ((size_t)b * Sn + t0) * Dn + d4;
    const float4* pC = reinterpret_cast<const float4*>(C + base);
    const float4* pV = reinterpret_cast<const float4*>(V + base);
    const float4* pW = reinterpret_cast<const float4*>(W + base);

    float P0 = 1.f, P1 = 1.f, P2 = 1.f, P3 = 1.f;
    float Q0 = 0.f, Q1 = 0.f, Q2 = 0.f, Q3 = 0.f;
    float AM = 1.f, AS = 0.f;

#pragma unroll
    for (int t = 0; t < Ln; ++t) {
        const float4 c = pC[t * (Dn / 4)];
        const float4 v = pV[t * (Dn / 4)];
        const float4 w = pW[t * (Dn / 4)];

        const float dd0 = fsig(w.x * tm.x), dd1 = fsig(w.y * tm.y);
        const float dd2 = fsig(w.z * tm.z), dd3 = fsig(w.w * tm.w);
        const float e0 = __expf(c.x), e1 = __expf(c.y);
        const float e2 = __expf(c.z), e3 = __expf(c.w);

        float ds = (dd0 + dd1) + (dd2 + dd3);
        float es = (e0 + e1) + (e2 + e3);
        warp_allreduce2(ds, es);
        const float m = ds * (1.0f / (float)Dn);
        if (lane == 0) {
            g_m[b * Sn + t0 + t] = m;
            g_s[b * Sn + t0 + t] = es;
        }
        AS = fmaf(m, AS, es);
        AM *= m;

        Q0 = fmaf(dd0, Q0, fmaf(e0, v.x, ctx0));
        Q1 = fmaf(dd1, Q1, fmaf(e1, v.y, ctx1));
        Q2 = fmaf(dd2, Q2, fmaf(e2, v.z, ctx2));
        Q3 = fmaf(dd3, Q3, fmaf(e3, v.w, ctx3));
        P0 *= dd0; P1 *= dd1; P2 *= dd2; P3 *= dd3;
    }

    const int agg = (b * NCn + k) * Dn + d4;
    *reinterpret_cast<float4*>(&g_P[agg]) = make_float4(P0, P1, P2, P3);
    *reinterpret_cast<float4*>(&g_Q[agg]) = make_float4(Q0, Q1, Q2, Q3);
    if (lane == 0) {
        g_AM[b * NCn + k] = AM;
        g_AS[b * NCn + k] = AS;
    }
}

// ============================================================================
// Pass B: serial combine over chunks (exclusive scan). One block per batch.
// 512 threads: (kq = tid>>7, d = tid&127). Staged shared loads keep LDGs
// parallel; the scan chain itself is only dependent FMAs.
// ============================================================================
__global__ void __launch_bounds__(512)
passB_kernel() {
    const int b = blockIdx.x;
    const int tid = threadIdx.x;
    const int d  = tid & (Dn - 1);
    const int kq = tid >> 7;   // 0..3

    __shared__ float sP[32][Dn];
    __shared__ float sQ[32][Dn];
    __shared__ float sAM[NCn];
    __shared__ float sAS[NCn];

    // stage scalar aggregates (512 threads, NCn == 512)
    sAM[tid] = g_AM[b * NCn + tid];
    sAS[tid] = g_AS[b * NCn + tid];
    __syncthreads();

    // scalar a-scan: all threads compute redundantly; thread 0 stores
    {
        float a = 0.f;
#pragma unroll 8
        for (int k = 0; k < NCn; ++k) {
            if (tid == 0) g_a0[b * NCn + k] = a;
            a = fmaf(sAM[k], a, sAS[k]);
        }
    }

    float b0 = 0.f;
    for (int st = 0; st < NCn / 32; ++st) {
        __syncthreads();
#pragma unroll
        for (int j = 0; j < 8; ++j) {
            const int kk = kq * 8 + j;
            const int k = st * 32 + kk;
            sP[kk][d] = g_P[(b * NCn + k) * Dn + d];
            sQ[kk][d] = g_Q[(b * NCn + k) * Dn + d];
        }
        __syncthreads();
        if (kq == 0) {
#pragma unroll
            for (int kk = 0; kk < 32; ++kk) {
                const int k = st * 32 + kk;
                g_b0[(b * NCn + k) * Dn + d] = b0;
                b0 = fmaf(sP[kk][d], b0, sQ[kk][d]);
            }
        }
    }
}

// ============================================================================
// Pass C: replay each chunk from its start state, emit LayerNorm'd output.
// One warp per (batch, chunk); lane owns 4 channels.
// ============================================================================
__global__ void __launch_bounds__(256)
passC_kernel(const float* __restrict__ C, const float* __restrict__ V,
             const float* __restrict__ W, const float* __restrict__ enc,
             const float* __restrict__ tmod, const float* __restrict__ cmod,
             const float* __restrict__ lnw, const float* __restrict__ lnb,
             float* __restrict__ out) {
    const int warp = (blockIdx.x * blockDim.x + threadIdx.x) >> 5;
    const int lane = threadIdx.x & 31;
    const int b = warp >> 9;
    const int k = warp & (NCn - 1);
    const int t0 = k * Ln;
    const int d4 = lane * 4;

    // lanes 0..Ln-1 hold the per-t scalars; broadcast via shuffle in the loop
    float mv = 0.f, sv = 0.f;
    if (lane < Ln) {
        mv = g_m[b * Sn + t0 + lane];
        sv = g_s[b * Sn + t0 + lane];
    }

    const float4 tm = *reinterpret_cast<const float4*>(tmod + d4);
    const float4 cm = *reinterpret_cast<const float4*>(cmod + d4);
    const float4 eb = *reinterpret_cast<const float4*>(enc + b * Dn + d4);
    const float ctx0 = fsig(eb.x * cm.x) * eb.x;
    const float ctx1 = fsig(eb.y * cm.y) * eb.y;
    const float ctx2 = fsig(eb.z * cm.z) * eb.z;
    const float ctx3 = fsig(eb.w * cm.w) * eb.w;
    const float4 w4 = *reinterpret_cast<const float4*>(lnw + d4);
    const float4 b4 = *reinterpret_cast<const float4*>(lnb + d4);

    float a = g_a0[b * NCn + k];
    float4 bst = *reinterpret_cast<const float4*>(&g_b0[(b * NCn + k) * Dn + d4]);

    const size_t base = ((size_t)b * Sn + t0) * Dn + d4;
    const float4* pC = reinterpret_cast<const float4*>(C + base);
    const float4* pV = reinterpret_cast<const float4*>(V + base);
    const float4* pW = reinterpret_cast<const float4*>(W + base);
    float4* pO = reinterpret_cast<float4*>(out + base);

#pragma unroll
    for (int t = 0; t < Ln; ++t) {
        const float4 c = pC[t * (Dn / 4)];
        const float4 v = pV[t * (Dn / 4)];
        const float4 w = pW[t * (Dn / 4)];

        const float dd0 = fsig(w.x * tm.x), dd1 = fsig(w.y * tm.y);
        const float dd2 = fsig(w.z * tm.z), dd3 = fsig(w.w * tm.w);
        const float e0 = __expf(c.x), e1 = __expf(c.y);
        const float e2 = __expf(c.z), e3 = __expf(c.w);

        const float m_t = __shfl_sync(0xffffffffu, mv, t);
        const float s_t = __shfl_sync(0xffffffffu, sv, t);
        a = fmaf(m_t, a, s_t);

        bst.x = fmaf(dd0, bst.x, fmaf(e0, v.x, ctx0));
        bst.y = fmaf(dd1, bst.y, fmaf(e1, v.y, ctx1));
        bst.z = fmaf(dd2, bst.z, fmaf(e2, v.z, ctx2));
        bst.w = fmaf(dd3, bst.w, fmaf(e3, v.w, ctx3));

        const float rinv = __fdividef(1.0f, a + 1e-8f);
        const float o0 = bst.x * rinv, o1 = bst.y * rinv;
        const float o2 = bst.z * rinv, o3 = bst.w * rinv;

        float lsum = (o0 + o1) + (o2 + o3);
        float lsq  = fmaf(o0, o0, fmaf(o1, o1, fmaf(o2, o2, o3 * o3)));
        warp_allreduce2(lsum, lsq);
        const float mu  = lsum * (1.0f / (float)Dn);
        const float var = fmaf(-mu, mu, lsq * (1.0f / (float)Dn));
        const float rstd = rsqrtf(var + 1e-5f);

        float4 r;
        r.x = fmaf((o0 - mu) * rstd, w4.x, b4.x);
        r.y = fmaf((o1 - mu) * rstd, w4.y, b4.y);
        r.z = fmaf((o2 - mu) * rstd, w4.z, b4.z);
        r.w = fmaf((o3 - mu) * rstd, w4.w, b4.w);
        pO[t * (Dn / 4)] = r;
    }
}

// ============================================================================
extern "C" void kernel_launch(void* const* d_in, const int* in_sizes, int n_in,
                              void* d_out, int out_size) {
    (void)in_sizes; (void)n_in; (void)out_size;
    const float* C    = (const float*)d_in[0];
    const float* V    = (const float*)d_in[1];
    const float* W    = (const float*)d_in[2];
    const float* enc  = (const float*)d_in[3];
    const float* tmod = (const float*)d_in[4];
    const float* cmod = (const float*)d_in[5];
    const float* lnw  = (const float*)d_in[6];
    const float* lnb  = (const float*)d_in[7];
    float* out = (float*)d_out;

    const int warpsTotal = Bn * NCn;            // 8192
    const int blocks = warpsTotal / 8;          // 1024 blocks of 256 threads

    passA_kernel<<<blocks, 256>>>(C, V, W, enc, tmod, cmod);
    passB_kernel<<<Bn, 512>>>();
    passC_kernel<<<blocks, 256>>>(C, V, W, enc, tmod, cmod, lnw, lnb, out);
}

// round 3
// speedup vs baseline: 1.0945x; 1.0945x over previous
#include <cuda_runtime.h>
#include <cstdint>

// Problem constants (fixed shapes per reference)
#define Bn 16
#define Sn 4096
#define Dn 128
#define Ln 8             // timesteps per chunk (data-parallel passes)
#define NCn (Sn / Ln)    // 512 chunks per batch
#define GC 32            // chunks per group (scan hierarchy)
#define NG (NCn / GC)    // 16 groups per batch
#define TG (GC * Ln)     // 256 timesteps per group

// -------- scratch (device globals; no allocation allowed) --------
__device__ float g_m   [Bn * Sn];          // per-t mean(decay)
__device__ float g_s   [Bn * Sn];          // per-t sum(exp(c))
__device__ float g_rinv[Bn * Sn];          // per-t 1/(a_t + eps)
__device__ float g_P   [Bn * NCn * Dn];    // chunk decay product per channel
__device__ float g_Q   [Bn * NCn * Dn];    // chunk additive term per channel
__device__ float g_b0  [Bn * NCn * Dn];    // bst at chunk start (exclusive)
__device__ float g_GP  [Bn * NG * Dn];     // group vector aggregates
__device__ float g_GQ  [Bn * NG * Dn];
__device__ float g_Gb0 [Bn * NG * Dn];     // bst at group start (exclusive)
__device__ float g_laneM[Bn * NG * 32];    // per-lane exclusive scalar prefixes
__device__ float g_laneS[Bn * NG * 32];
__device__ float g_GAM [Bn * NG];          // group scalar aggregates (M, S)
__device__ float g_GAS [Bn * NG];
__device__ float g_Ga0 [Bn * NG];          // a at group start (exclusive)

__device__ __forceinline__ float fsig(float x) {
    return __fdividef(1.0f, 1.0f + __expf(-x));
}

__device__ __forceinline__ void warp_allreduce2(float& x, float& y) {
#pragma unroll
    for (int off = 16; off; off >>= 1) {
        x += __shfl_xor_sync(0xffffffffu, x, off);
        y += __shfl_xor_sync(0xffffffffu, y, off);
    }
}

// ============================================================================
// Pass A: per-chunk aggregates. One warp per (batch, chunk); lane owns 4 ch.
// ============================================================================
__global__ void __launch_bounds__(256)
passA_kernel(const float* __restrict__ C, const float* __restrict__ V,
             const float* __restrict__ W, const float* __restrict__ enc,
             const float* __restrict__ tmod, const float* __restrict__ cmod) {
    const int warp = (blockIdx.x * blockDim.x + threadIdx.x) >> 5;
    const int lane = threadIdx.x & 31;
    const int b = warp >> 9;          // / NCn
    const int k = warp & (NCn - 1);
    const int t0 = k * Ln;
    const int d4 = lane * 4;

    const float4 tm = *reinterpret_cast<const float4*>(tmod + d4);
    const float4 cm = *reinterpret_cast<const float4*>(cmod + d4);
    const float4 eb = *reinterpret_cast<const float4*>(enc + b * Dn + d4);
    const float ctx0 = fsig(eb.x * cm.x) * eb.x;
    const float ctx1 = fsig(eb.y * cm.y) * eb.y;
    const float ctx2 = fsig(eb.z * cm.z) * eb.z;
    const float ctx3 = fsig(eb.w * cm.w) * eb.w;

    const size_t base = ((size_t)b * Sn + t0) * Dn + d4;
    const float4* pC = reinterpret_cast<const float4*>(C + base);
    const float4* pV = reinterpret_cast<const float4*>(V + base);
    const float4* pW = reinterpret_cast<const float4*>(W + base);

    float P0 = 1.f, P1 = 1.f, P2 = 1.f, P3 = 1.f;
    float Q0 = 0.f, Q1 = 0.f, Q2 = 0.f, Q3 = 0.f;

#pragma unroll
    for (int t = 0; t < Ln; ++t) {
        const float4 c = pC[t * (Dn / 4)];
        const float4 v = pV[t * (Dn / 4)];
        const float4 w = pW[t * (Dn / 4)];

        const float dd0 = fsig(w.x * tm.x), dd1 = fsig(w.y * tm.y);
        const float dd2 = fsig(w.z * tm.z), dd3 = fsig(w.w * tm.w);
        const float e0 = __expf(c.x), e1 = __expf(c.y);
        const float e2 = __expf(c.z), e3 = __expf(c.w);

        float ds = (dd0 + dd1) + (dd2 + dd3);
        float es = (e0 + e1) + (e2 + e3);
        warp_allreduce2(ds, es);
        if (lane == 0) {
            g_m[b * Sn + t0 + t] = ds * (1.0f / (float)Dn);
            g_s[b * Sn + t0 + t] = es;
        }

        Q0 = fmaf(dd0, Q0, fmaf(e0, v.x, ctx0));
        Q1 = fmaf(dd1, Q1, fmaf(e1, v.y, ctx1));
        Q2 = fmaf(dd2, Q2, fmaf(e2, v.z, ctx2));
        Q3 = fmaf(dd3, Q3, fmaf(e3, v.w, ctx3));
        P0 *= dd0; P1 *= dd1; P2 *= dd2; P3 *= dd3;
    }

    const int agg = (b * NCn + k) * Dn + d4;
    *reinterpret_cast<float4*>(&g_P[agg]) = make_float4(P0, P1, P2, P3);
    *reinterpret_cast<float4*>(&g_Q[agg]) = make_float4(Q0, Q1, Q2, Q3);
}

// ============================================================================
// Pass B1: group aggregates (parallel). One CTA per (batch, group).
//   threads 0..127: compose 32 chunk (P,Q) -> group (GP,GQ) for channel d
//   warp 0 also: scalar affine scan over 256 timesteps (8 serial per lane +
//   shfl compose), storing per-lane exclusive prefixes + group aggregate.
// ============================================================================
__global__ void __launch_bounds__(128)
passB1_kernel() {
    const int b = blockIdx.x / NG;
    const int g = blockIdx.x % NG;
    const int d = threadIdx.x;

    // vector group aggregate
    {
        float P = 1.f, Q = 0.f;
#pragma unroll 8
        for (int kk = 0; kk < GC; ++kk) {
            const int idx = (b * NCn + g * GC + kk) * Dn + d;
            const float Pk = g_P[idx], Qk = g_Q[idx];
            Q = fmaf(Pk, Q, Qk);
            P *= Pk;
        }
        g_GP[(b * NG + g) * Dn + d] = P;
        g_GQ[(b * NG + g) * Dn + d] = Q;
    }

    // scalar group scan (warp 0 only)
    if (threadIdx.x < 32) {
        const int lane = threadIdx.x;
        const int tb = b * Sn + g * TG + lane * Ln;
        float M = 1.f, S = 0.f;
#pragma unroll
        for (int i = 0; i < Ln; ++i) {
            const float m = g_m[tb + i], s = g_s[tb + i];
            S = fmaf(m, S, s);
            M *= m;
        }
        // inclusive affine compose scan across lanes
#pragma unroll
        for (int off = 1; off < 32; off <<= 1) {
            const float Mp = __shfl_up_sync(0xffffffffu, M, off);
            const float Sp = __shfl_up_sync(0xffffffffu, S, off);
            if (lane >= off) {
                S = fmaf(M, Sp, S);
                M = M * Mp;
            }
        }
        // exclusive prefix = inclusive of lane-1
        float Mex = __shfl_up_sync(0xffffffffu, M, 1);
        float Sex = __shfl_up_sync(0xffffffffu, S, 1);
        if (lane == 0) { Mex = 1.f; Sex = 0.f; }
        g_laneM[(b * NG + g) * 32 + lane] = Mex;
        g_laneS[(b * NG + g) * 32 + lane] = Sex;
        if (lane == 31) {
            g_GAM[b * NG + g] = M;
            g_GAS[b * NG + g] = S;
        }
    }
}

// ============================================================================
// Pass B2: serial scan over 16 groups per batch (the only serial part).
// ============================================================================
__global__ void __launch_bounds__(128)
passB2_kernel() {
    const int b = blockIdx.x;
    const int d = threadIdx.x;

    float bp = 0.f;
#pragma unroll
    for (int g = 0; g < NG; ++g) {
        const int idx = (b * NG + g) * Dn + d;
        g_Gb0[idx] = bp;
        bp = fmaf(g_GP[idx], bp, g_GQ[idx]);
    }

    if (d == 0) {
        float a = 0.f;
#pragma unroll
        for (int g = 0; g < NG; ++g) {
            g_Ga0[b * NG + g] = a;
            a = fmaf(g_GAM[b * NG + g], a, g_GAS[b * NG + g]);
        }
    }
}

// ============================================================================
// Pass B3: distribute prefixes down (parallel). One CTA per (batch, group).
//   threads 0..127: rescan 32 chunks writing g_b0 (channel d)
//   warp 0 also: rescan scalars writing g_rinv for all 256 timesteps
// ============================================================================
__global__ void __launch_bounds__(128)
passB3_kernel() {
    const int b = blockIdx.x / NG;
    const int g = blockIdx.x % NG;
    const int d = threadIdx.x;

    {
        float b0 = g_Gb0[(b * NG + g) * Dn + d];
#pragma unroll 8
        for (int kk = 0; kk < GC; ++kk) {
            const int idx = (b * NCn + g * GC + kk) * Dn + d;
            g_b0[idx] = b0;
            b0 = fmaf(g_P[idx], b0, g_Q[idx]);
        }
    }

    if (threadIdx.x < 32) {
        const int lane = threadIdx.x;
        const float a0g = g_Ga0[b * NG + g];
        const float Mex = g_laneM[(b * NG + g) * 32 + lane];
        const float Sex = g_laneS[(b * NG + g) * 32 + lane];
        float a = fmaf(Mex, a0g, Sex);
        const int tb = b * Sn + g * TG + lane * Ln;
#pragma unroll
        for (int i = 0; i < Ln; ++i) {
            a = fmaf(g_m[tb + i], a, g_s[tb + i]);
            g_rinv[tb + i] = __fdividef(1.0f, a + 1e-8f);
        }
    }
}

// ============================================================================
// Pass C: replay each chunk from its start state, emit LayerNorm'd output.
// One warp per (batch, chunk); lane owns 4 channels. No serial scalar chain:
// rinv_t is precomputed.
// ============================================================================
__global__ void __launch_bounds__(256)
passC_kernel(const float* __restrict__ C, const float* __restrict__ V,
             const float* __restrict__ W, const float* __restrict__ enc,
             const float* __restrict__ tmod, const float* __restrict__ cmod,
             const float* __restrict__ lnw, const float* __restrict__ lnb,
             float* __restrict__ out) {
    const int warp = (blockIdx.x * blockDim.x + threadIdx.x) >> 5;
    const int lane = threadIdx.x & 31;
    const int b = warp >> 9;
    const int k = warp & (NCn - 1);
    const int t0 = k * Ln;
    const int d4 = lane * 4;

    // lanes 0..Ln-1 hold precomputed rinv; broadcast via shuffle in the loop
    float rv = 0.f;
    if (lane < Ln) rv = g_rinv[b * Sn + t0 + lane];

    const float4 tm = *reinterpret_cast<const float4*>(tmod + d4);
    const float4 cm = *reinterpret_cast<const float4*>(cmod + d4);
    const float4 eb = *reinterpret_cast<const float4*>(enc + b * Dn + d4);
    const float ctx0 = fsig(eb.x * cm.x) * eb.x;
    const float ctx1 = fsig(eb.y * cm.y) * eb.y;
    const float ctx2 = fsig(eb.z * cm.z) * eb.z;
    const float ctx3 = fsig(eb.w * cm.w) * eb.w;
    const float4 w4 = *reinterpret_cast<const float4*>(lnw + d4);
    const float4 b4 = *reinterpret_cast<const float4*>(lnb + d4);

    float4 bst = *reinterpret_cast<const float4*>(&g_b0[(b * NCn + k) * Dn + d4]);

    const size_t base = ((size_t)b * Sn + t0) * Dn + d4;
    const float4* pC = reinterpret_cast<const float4*>(C + base);
    const float4* pV = reinterpret_cast<const float4*>(V + base);
    const float4* pW = reinterpret_cast<const float4*>(W + base);
    float4* pO = reinterpret_cast<float4*>(out + base);

#pragma unroll
    for (int t = 0; t < Ln; ++t) {
        const float4 c = pC[t * (Dn / 4)];
        const float4 v = pV[t * (Dn / 4)];
        const float4 w = pW[t * (Dn / 4)];

        const float dd0 = fsig(w.x * tm.x), dd1 = fsig(w.y * tm.y);
        const float dd2 = fsig(w.z * tm.z), dd3 = fsig(w.w * tm.w);
        const float e0 = __expf(c.x), e1 = __expf(c.y);
        const float e2 = __expf(c.z), e3 = __expf(c.w);

        bst.x = fmaf(dd0, bst.x, fmaf(e0, v.x, ctx0));
        bst.y = fmaf(dd1, bst.y, fmaf(e1, v.y, ctx1));
        bst.z = fmaf(dd2, bst.z, fmaf(e2, v.z, ctx2));
        bst.w = fmaf(dd3, bst.w, fmaf(e3, v.w, ctx3));

        const float rinv = __shfl_sync(0xffffffffu, rv, t);
        const float o0 = bst.x * rinv, o1 = bst.y * rinv;
        const float o2 = bst.z * rinv, o3 = bst.w * rinv;

        float lsum = (o0 + o1) + (o2 + o3);
        float lsq  = fmaf(o0, o0, fmaf(o1, o1, fmaf(o2, o2, o3 * o3)));
        warp_allreduce2(lsum, lsq);
        const float mu  = lsum * (1.0f / (float)Dn);
        const float var = fmaf(-mu, mu, lsq * (1.0f / (float)Dn));
        const float rstd = rsqrtf(var + 1e-5f);

        float4 r;
        r.x = fmaf((o0 - mu) * rstd, w4.x, b4.x);
        r.y = fmaf((o1 - mu) * rstd, w4.y, b4.y);
        r.z = fmaf((o2 - mu) * rstd, w4.z, b4.z);
        r.w = fmaf((o3 - mu) * rstd, w4.w, b4.w);
        pO[t * (Dn / 4)] = r;
    }
}

// ============================================================================
extern "C" void kernel_launch(void* const* d_in, const int* in_sizes, int n_in,
                              void* d_out, int out_size) {
    (void)in_sizes; (void)n_in; (void)out_size;
    const float* C    = (const float*)d_in[0];
    const float* V    = (const float*)d_in[1];
    const float* W    = (const float*)d_in[2];
    const float* enc  = (const float*)d_in[3];
    const float* tmod = (const float*)d_in[4];
    const float* cmod = (const float*)d_in[5];
    const float* lnw  = (const float*)d_in[6];
    const float* lnb  = (const float*)d_in[7];
    float* out = (float*)d_out;

    const int warpsTotal = Bn * NCn;            // 8192
    const int blocks = warpsTotal / 8;          // 1024 blocks of 256 threads

    passA_kernel<<<blocks, 256>>>(C, V, W, enc, tmod, cmod);
    passB1_kernel<<<Bn * NG, 128>>>();
    passB2_kernel<<<Bn, 128>>>();
    passB3_kernel<<<Bn * NG, 128>>>();
    passC_kernel<<<blocks, 256>>>(C, V, W, enc, tmod, cmod, lnw, lnb, out);
}

// round 4
// speedup vs baseline: 1.2876x; 1.1764x over previous
#include <cuda_runtime.h>
#include <cstdint>

// Problem constants (fixed shapes per reference)
#define Bn 16
#define Sn 4096
#define Dn 128
#define Ln 8             // timesteps per chunk (data-parallel passes)
#define NCn (Sn / Ln)    // 512 chunks per batch
#define GC 16            // chunks per group (scan hierarchy)
#define NG (NCn / GC)    // 32 groups per batch
#define TG (GC * Ln)     // 128 timesteps per group
#define LPL (TG / 32)    // 4 timesteps per lane in group scalar scan

// -------- scratch (device globals; no allocation allowed) --------
__device__ float g_m   [Bn * Sn];          // per-t mean(decay)
__device__ float g_s   [Bn * Sn];          // per-t sum(exp(c))
__device__ float g_rinv[Bn * Sn];          // per-t 1/(a_t + eps)
__device__ float g_P   [Bn * NCn * Dn];    // chunk decay product per channel
__device__ float g_Q   [Bn * NCn * Dn];    // chunk additive term per channel
__device__ float g_b0  [Bn * NCn * Dn];    // bst at chunk start (exclusive)
__device__ float g_GP  [Bn * NG * Dn];     // group vector aggregates
__device__ float g_GQ  [Bn * NG * Dn];
__device__ float g_Gb0 [Bn * NG * Dn];     // bst at group start (exclusive)
__device__ float g_laneM[Bn * NG * 32];    // per-lane exclusive scalar prefixes
__device__ float g_laneS[Bn * NG * 32];
__device__ float g_GAM [Bn * NG];          // group scalar aggregates (M, S)
__device__ float g_GAS [Bn * NG];
__device__ float g_Ga0 [Bn * NG];          // a at group start (exclusive)

__device__ __forceinline__ float fsig(float x) {
    return __fdividef(1.0f, 1.0f + __expf(-x));
}

__device__ __forceinline__ void warp_allreduce2(float& x, float& y) {
#pragma unroll
    for (int off = 16; off; off >>= 1) {
        x += __shfl_xor_sync(0xffffffffu, x, off);
        y += __shfl_xor_sync(0xffffffffu, y, off);
    }
}

// ============================================================================
// Pass A: per-chunk aggregates. One warp per (batch, chunk); lane owns 4 ch.
// ============================================================================
__global__ void __launch_bounds__(256)
passA_kernel(const float* __restrict__ C, const float* __restrict__ V,
             const float* __restrict__ W, const float* __restrict__ enc,
             const float* __restrict__ tmod, const float* __restrict__ cmod) {
    const int warp = (blockIdx.x * blockDim.x + threadIdx.x) >> 5;
    const int lane = threadIdx.x & 31;
    const int b = warp >> 9;          // / NCn
    const int k = warp & (NCn - 1);
    const int t0 = k * Ln;
    const int d4 = lane * 4;

    const float4 tm = *reinterpret_cast<const float4*>(tmod + d4);
    const float4 cm = *reinterpret_cast<const float4*>(cmod + d4);
    const float4 eb = *reinterpret_cast<const float4*>(enc + b * Dn + d4);
    const float ctx0 = fsig(eb.x * cm.x) * eb.x;
    const float ctx1 = fsig(eb.y * cm.y) * eb.y;
    const float ctx2 = fsig(eb.z * cm.z) * eb.z;
    const float ctx3 = fsig(eb.w * cm.w) * eb.w;

    const size_t base = ((size_t)b * Sn + t0) * Dn + d4;
    const float4* pC = reinterpret_cast<const float4*>(C + base);
    const float4* pV = reinterpret_cast<const float4*>(V + base);
    const float4* pW = reinterpret_cast<const float4*>(W + base);

    float P0 = 1.f, P1 = 1.f, P2 = 1.f, P3 = 1.f;
    float Q0 = 0.f, Q1 = 0.f, Q2 = 0.f, Q3 = 0.f;

#pragma unroll
    for (int t = 0; t < Ln; ++t) {
        const float4 c = pC[t * (Dn / 4)];
        const float4 v = pV[t * (Dn / 4)];
        const float4 w = pW[t * (Dn / 4)];

        const float dd0 = fsig(w.x * tm.x), dd1 = fsig(w.y * tm.y);
        const float dd2 = fsig(w.z * tm.z), dd3 = fsig(w.w * tm.w);
        const float e0 = __expf(c.x), e1 = __expf(c.y);
        const float e2 = __expf(c.z), e3 = __expf(c.w);

        float ds = (dd0 + dd1) + (dd2 + dd3);
        float es = (e0 + e1) + (e2 + e3);
        warp_allreduce2(ds, es);
        if (lane == 0) {
            g_m[b * Sn + t0 + t] = ds * (1.0f / (float)Dn);
            g_s[b * Sn + t0 + t] = es;
        }

        Q0 = fmaf(dd0, Q0, fmaf(e0, v.x, ctx0));
        Q1 = fmaf(dd1, Q1, fmaf(e1, v.y, ctx1));
        Q2 = fmaf(dd2, Q2, fmaf(e2, v.z, ctx2));
        Q3 = fmaf(dd3, Q3, fmaf(e3, v.w, ctx3));
        P0 *= dd0; P1 *= dd1; P2 *= dd2; P3 *= dd3;
    }

    const int agg = (b * NCn + k) * Dn + d4;
    *reinterpret_cast<float4*>(&g_P[agg]) = make_float4(P0, P1, P2, P3);
    *reinterpret_cast<float4*>(&g_Q[agg]) = make_float4(Q0, Q1, Q2, Q3);
}

// ============================================================================
// Pass B1: group aggregates (parallel). One CTA per (batch, group).
// Register-prefetch all loads, then run the pure-FMA chains.
// ============================================================================
__global__ void __launch_bounds__(128)
passB1_kernel() {
    const int b = blockIdx.x >> 5;        // / NG
    const int g = blockIdx.x & (NG - 1);
    const int d = threadIdx.x;

    // ---- vector group aggregate: prefetch GC (P,Q) pairs, then chain ----
    float Pr[GC], Qr[GC];
#pragma unroll
    for (int kk = 0; kk < GC; ++kk) {
        const int idx = (b * NCn + g * GC + kk) * Dn + d;
        Pr[kk] = g_P[idx];
        Qr[kk] = g_Q[idx];
    }
    float P = Pr[0], Q = Qr[0];
#pragma unroll
    for (int kk = 1; kk < GC; ++kk) {
        Q = fmaf(Pr[kk], Q, Qr[kk]);
        P *= Pr[kk];
    }
    g_GP[(b * NG + g) * Dn + d] = P;
    g_GQ[(b * NG + g) * Dn + d] = Q;

    // ---- scalar group scan (warp 0): LPL per lane + shfl affine scan ----
    if (threadIdx.x < 32) {
        const int lane = threadIdx.x;
        const int tb = b * Sn + g * TG + lane * LPL;
        float mr[LPL], sr[LPL];
#pragma unroll
        for (int i = 0; i < LPL; ++i) { mr[i] = g_m[tb + i]; sr[i] = g_s[tb + i]; }
        float M = mr[0], S = sr[0];
#pragma unroll
        for (int i = 1; i < LPL; ++i) { S = fmaf(mr[i], S, sr[i]); M *= mr[i]; }
#pragma unroll
        for (int off = 1; off < 32; off <<= 1) {
            const float Mp = __shfl_up_sync(0xffffffffu, M, off);
            const float Sp = __shfl_up_sync(0xffffffffu, S, off);
            if (lane >= off) { S = fmaf(M, Sp, S); M = M * Mp; }
        }
        float Mex = __shfl_up_sync(0xffffffffu, M, 1);
        float Sex = __shfl_up_sync(0xffffffffu, S, 1);
        if (lane == 0) { Mex = 1.f; Sex = 0.f; }
        g_laneM[(b * NG + g) * 32 + lane] = Mex;
        g_laneS[(b * NG + g) * 32 + lane] = Sex;
        if (lane == 31) {
            g_GAM[b * NG + g] = M;
            g_GAS[b * NG + g] = S;
        }
    }
}

// ============================================================================
// Pass B2: serial scan over NG=32 groups per batch. One CTA per batch.
// Vector: 32-deep register chain (prefetched). Scalar: warp shfl affine scan.
// ============================================================================
__global__ void __launch_bounds__(128)
passB2_kernel() {
    const int b = blockIdx.x;
    const int d = threadIdx.x;

    float Pr[NG], Qr[NG];
#pragma unroll
    for (int g = 0; g < NG; ++g) {
        const int idx = (b * NG + g) * Dn + d;
        Pr[g] = g_GP[idx];
        Qr[g] = g_GQ[idx];
    }
    float bp = 0.f;
#pragma unroll
    for (int g = 0; g < NG; ++g) {
        g_Gb0[(b * NG + g) * Dn + d] = bp;
        bp = fmaf(Pr[g], bp, Qr[g]);
    }

    // scalar: warp 0, lane = group index (NG == 32)
    if (threadIdx.x < 32) {
        const int lane = threadIdx.x;
        float M = g_GAM[b * NG + lane];
        float S = g_GAS[b * NG + lane];
#pragma unroll
        for (int off = 1; off < 32; off <<= 1) {
            const float Mp = __shfl_up_sync(0xffffffffu, M, off);
            const float Sp = __shfl_up_sync(0xffffffffu, S, off);
            if (lane >= off) { S = fmaf(M, Sp, S); M = M * Mp; }
        }
        // exclusive prefix
        float Sex = __shfl_up_sync(0xffffffffu, S, 1);
        if (lane == 0) Sex = 0.f;
        g_Ga0[b * NG + lane] = Sex;   // a starts at 0, so a0(group) = Sex
    }
}

// ============================================================================
// Pass B3: distribute prefixes down (parallel). One CTA per (batch, group).
// ============================================================================
__global__ void __launch_bounds__(128)
passB3_kernel() {
    const int b = blockIdx.x >> 5;
    const int g = blockIdx.x & (NG - 1);
    const int d = threadIdx.x;

    // ---- vector rescan: prefetch, then chain + stores ----
    {
        float Pr[GC], Qr[GC];
#pragma unroll
        for (int kk = 0; kk < GC; ++kk) {
            const int idx = (b * NCn + g * GC + kk) * Dn + d;
            Pr[kk] = g_P[idx];
            Qr[kk] = g_Q[idx];
        }
        float b0 = g_Gb0[(b * NG + g) * Dn + d];
#pragma unroll
        for (int kk = 0; kk < GC; ++kk) {
            g_b0[(b * NCn + g * GC + kk) * Dn + d] = b0;
            b0 = fmaf(Pr[kk], b0, Qr[kk]);
        }
    }

    // ---- scalar rescan: write rinv for all TG timesteps ----
    if (threadIdx.x < 32) {
        const int lane = threadIdx.x;
        const float a0g = g_Ga0[b * NG + g];
        const float Mex = g_laneM[(b * NG + g) * 32 + lane];
        const float Sex = g_laneS[(b * NG + g) * 32 + lane];
        const int tb = b * Sn + g * TG + lane * LPL;
        float mr[LPL], sr[LPL];
#pragma unroll
        for (int i = 0; i < LPL; ++i) { mr[i] = g_m[tb + i]; sr[i] = g_s[tb + i]; }
        float a = fmaf(Mex, a0g, Sex);
#pragma unroll
        for (int i = 0; i < LPL; ++i) {
            a = fmaf(mr[i], a, sr[i]);
            g_rinv[tb + i] = __fdividef(1.0f, a + 1e-8f);
        }
    }
}

// ============================================================================
// Pass C: replay each chunk from its start state, emit LayerNorm'd output.
// One warp per (batch, chunk); lane owns 4 channels. rinv precomputed.
// ============================================================================
__global__ void __launch_bounds__(256)
passC_kernel(const float* __restrict__ C, const float* __restrict__ V,
             const float* __restrict__ W, const float* __restrict__ enc,
             const float* __restrict__ tmod, const float* __restrict__ cmod,
             const float* __restrict__ lnw, const float* __restrict__ lnb,
             float* __restrict__ out) {
    const int warp = (blockIdx.x * blockDim.x + threadIdx.x) >> 5;
    const int lane = threadIdx.x & 31;
    const int b = warp >> 9;
    const int k = warp & (NCn - 1);
    const int t0 = k * Ln;
    const int d4 = lane * 4;

    float rv = 0.f;
    if (lane < Ln) rv = g_rinv[b * Sn + t0 + lane];

    const float4 tm = *reinterpret_cast<const float4*>(tmod + d4);
    const float4 cm = *reinterpret_cast<const float4*>(cmod + d4);
    const float4 eb = *reinterpret_cast<const float4*>(enc + b * Dn + d4);
    const float ctx0 = fsig(eb.x * cm.x) * eb.x;
    const float ctx1 = fsig(eb.y * cm.y) * eb.y;
    const float ctx2 = fsig(eb.z * cm.z) * eb.z;
    const float ctx3 = fsig(eb.w * cm.w) * eb.w;
    const float4 w4 = *reinterpret_cast<const float4*>(lnw + d4);
    const float4 b4 = *reinterpret_cast<const float4*>(lnb + d4);

    float4 bst = *reinterpret_cast<const float4*>(&g_b0[(b * NCn + k) * Dn + d4]);

    const size_t base = ((size_t)b * Sn + t0) * Dn + d4;
    const float4* pC = reinterpret_cast<const float4*>(C + base);
    const float4* pV = reinterpret_cast<const float4*>(V + base);
    const float4* pW = reinterpret_cast<const float4*>(W + base);
    float4* pO = reinterpret_cast<float4*>(out + base);

#pragma unroll
    for (int t = 0; t < Ln; ++t) {
        const float4 c = pC[t * (Dn / 4)];
        const float4 v = pV[t * (Dn / 4)];
        const float4 w = pW[t * (Dn / 4)];

        const float dd0 = fsig(w.x * tm.x), dd1 = fsig(w.y * tm.y);
        const float dd2 = fsig(w.z * tm.z), dd3 = fsig(w.w * tm.w);
        const float e0 = __expf(c.x), e1 = __expf(c.y);
        const float e2 = __expf(c.z), e3 = __expf(c.w);

        bst.x = fmaf(dd0, bst.x, fmaf(e0, v.x, ctx0));
        bst.y = fmaf(dd1, bst.y, fmaf(e1, v.y, ctx1));
        bst.z = fmaf(dd2, bst.z, fmaf(e2, v.z, ctx2));
        bst.w = fmaf(dd3, bst.w, fmaf(e3, v.w, ctx3));

        const float rinv = __shfl_sync(0xffffffffu, rv, t);
        const float o0 = bst.x * rinv, o1 = bst.y * rinv;
        const float o2 = bst.z * rinv, o3 = bst.w * rinv;

        float lsum = (o0 + o1) + (o2 + o3);
        float lsq  = fmaf(o0, o0, fmaf(o1, o1, fmaf(o2, o2, o3 * o3)));
        warp_allreduce2(lsum, lsq);
        const float mu  = lsum * (1.0f / (float)Dn);
        const float var = fmaf(-mu, mu, lsq * (1.0f / (float)Dn));
        const float rstd = rsqrtf(var + 1e-5f);

        float4 r;
        r.x = fmaf((o0 - mu) * rstd, w4.x, b4.x);
        r.y = fmaf((o1 - mu) * rstd, w4.y, b4.y);
        r.z = fmaf((o2 - mu) * rstd, w4.z, b4.z);
        r.w = fmaf((o3 - mu) * rstd, w4.w, b4.w);
        pO[t * (Dn / 4)] = r;
    }
}

// ============================================================================
extern "C" void kernel_launch(void* const* d_in, const int* in_sizes, int n_in,
                              void* d_out, int out_size) {
    (void)in_sizes; (void)n_in; (void)out_size;
    const float* C    = (const float*)d_in[0];
    const float* V    = (const float*)d_in[1];
    const float* W    = (const float*)d_in[2];
    const float* enc  = (const float*)d_in[3];
    const float* tmod = (const float*)d_in[4];
    const float* cmod = (const float*)d_in[5];
    const float* lnw  = (const float*)d_in[6];
    const float* lnb  = (const float*)d_in[7];
    float* out = (float*)d_out;

    const int warpsTotal = Bn * NCn;            // 8192
    const int blocks = warpsTotal / 8;          // 1024 blocks of 256 threads

    passA_kernel<<<blocks, 256>>>(C, V, W, enc, tmod, cmod);
    passB1_kernel<<<Bn * NG, 128>>>();
    passB2_kernel<<<Bn, 128>>>();
    passB3_kernel<<<Bn * NG, 128>>>();
    passC_kernel<<<blocks, 256>>>(C, V, W, enc, tmod, cmod, lnw, lnb, out);
}

// round 6
// speedup vs baseline: 1.5127x; 1.1748x over previous
#include <cuda_runtime.h>
#include <cstdint>

// Problem constants (fixed shapes per reference)
#define Bn 16
#define Sn 4096
#define Dn 128
#define Ln 8             // timesteps per chunk (data-parallel passes)
#define NCn (Sn / Ln)    // 512 chunks per batch
#define GC 16            // chunks per group (scan hierarchy)
#define NG (NCn / GC)    // 32 groups per batch
#define TG (GC * Ln)     // 128 timesteps per group
#define LPL (TG / 32)    // 4 timesteps per lane in group scalar scan

// -------- scratch (device globals; no allocation allowed) --------
__device__ float g_m   [Bn * Sn];          // per-t mean(decay)
__device__ float g_s   [Bn * Sn];          // per-t sum(exp(c))
__device__ float g_rinv[Bn * Sn];          // per-t 1/(a_t + eps)
__device__ float g_P   [Bn * NCn * Dn];    // chunk decay product per channel
__device__ float g_Q   [Bn * NCn * Dn];    // chunk additive term per channel
__device__ float g_b0  [Bn * NCn * Dn];    // bst at chunk start (exclusive)
__device__ float g_GP  [Bn * NG * Dn];     // group vector aggregates
__device__ float g_GQ  [Bn * NG * Dn];
__device__ float g_laneM[Bn * NG * 32];    // per-lane exclusive scalar prefixes
__device__ float g_laneS[Bn * NG * 32];
__device__ float g_GAM [Bn * NG];          // group scalar aggregates (M, S)
__device__ float g_GAS [Bn * NG];

__device__ __forceinline__ float fsig(float x) {
    return __fdividef(1.0f, 1.0f + __expf(-x));
}

__device__ __forceinline__ void warp_allreduce2(float& x, float& y) {
#pragma unroll
    for (int off = 16; off; off >>= 1) {
        x += __shfl_xor_sync(0xffffffffu, x, off);
        y += __shfl_xor_sync(0xffffffffu, y, off);
    }
}

// ---- cache-policy loads/stores (createpolicy + L2::cache_hint form) --------
// passA reads inputs with evict_last so the ~100 MB working set stays in the
// ~126 MB L2; passC re-reads with evict_first. passC output is streamed (cs).
__device__ __forceinline__ uint64_t pol_evict_last() {
    uint64_t p;
    asm("createpolicy.fractional.L2::evict_last.b64 %0, 1.0;" : "=l"(p));
    return p;
}
__device__ __forceinline__ uint64_t pol_evict_first() {
    uint64_t p;
    asm("createpolicy.fractional.L2::evict_first.b64 %0, 1.0;" : "=l"(p));
    return p;
}
__device__ __forceinline__ float4 ldg_pol(const float4* p, uint64_t pol) {
    float4 r;
    asm volatile("ld.global.nc.L2::cache_hint.v4.f32 {%0,%1,%2,%3}, [%4], %5;"
                 : "=f"(r.x), "=f"(r.y), "=f"(r.z), "=f"(r.w)
                 : "l"(p), "l"(pol));
    return r;
}
__device__ __forceinline__ void stg_stream(float4* p, float4 v) {
    asm volatile("st.global.cs.v4.f32 [%0], {%1,%2,%3,%4};"
                 :: "l"(p), "f"(v.x), "f"(v.y), "f"(v.z), "f"(v.w) : "memory");
}

// ============================================================================
// Pass A: per-chunk aggregates. One warp per (batch, chunk); lane owns 4 ch.
// ============================================================================
__global__ void __launch_bounds__(256)
passA_kernel(const float* __restrict__ C, const float* __restrict__ V,
             const float* __restrict__ W, const float* __restrict__ enc,
             const float* __restrict__ tmod, const float* __restrict__ cmod) {
    const int warp = (blockIdx.x * blockDim.x + threadIdx.x) >> 5;
    const int lane = threadIdx.x & 31;
    const int b = warp >> 9;          // / NCn
    const int k = warp & (NCn - 1);
    const int t0 = k * Ln;
    const int d4 = lane * 4;

    const uint64_t pol = pol_evict_last();

    const float4 tm = *reinterpret_cast<const float4*>(tmod + d4);
    const float4 cm = *reinterpret_cast<const float4*>(cmod + d4);
    const float4 eb = *reinterpret_cast<const float4*>(enc + b * Dn + d4);
    const float ctx0 = fsig(eb.x * cm.x) * eb.x;
    const float ctx1 = fsig(eb.y * cm.y) * eb.y;
    const float ctx2 = fsig(eb.z * cm.z) * eb.z;
    const float ctx3 = fsig(eb.w * cm.w) * eb.w;

    const size_t base = ((size_t)b * Sn + t0) * Dn + d4;
    const float4* pC = reinterpret_cast<const float4*>(C + base);
    const float4* pV = reinterpret_cast<const float4*>(V + base);
    const float4* pW = reinterpret_cast<const float4*>(W + base);

    float P0 = 1.f, P1 = 1.f, P2 = 1.f, P3 = 1.f;
    float Q0 = 0.f, Q1 = 0.f, Q2 = 0.f, Q3 = 0.f;

#pragma unroll
    for (int t = 0; t < Ln; ++t) {
        const float4 c = ldg_pol(pC + t * (Dn / 4), pol);
        const float4 v = ldg_pol(pV + t * (Dn / 4), pol);
        const float4 w = ldg_pol(pW + t * (Dn / 4), pol);

        const float dd0 = fsig(w.x * tm.x), dd1 = fsig(w.y * tm.y);
        const float dd2 = fsig(w.z * tm.z), dd3 = fsig(w.w * tm.w);
        const float e0 = __expf(c.x), e1 = __expf(c.y);
        const float e2 = __expf(c.z), e3 = __expf(c.w);

        float ds = (dd0 + dd1) + (dd2 + dd3);
        float es = (e0 + e1) + (e2 + e3);
        warp_allreduce2(ds, es);
        if (lane == 0) {
            g_m[b * Sn + t0 + t] = ds * (1.0f / (float)Dn);
            g_s[b * Sn + t0 + t] = es;
        }

        Q0 = fmaf(dd0, Q0, fmaf(e0, v.x, ctx0));
        Q1 = fmaf(dd1, Q1, fmaf(e1, v.y, ctx1));
        Q2 = fmaf(dd2, Q2, fmaf(e2, v.z, ctx2));
        Q3 = fmaf(dd3, Q3, fmaf(e3, v.w, ctx3));
        P0 *= dd0; P1 *= dd1; P2 *= dd2; P3 *= dd3;
    }

    const int agg = (b * NCn + k) * Dn + d4;
    *reinterpret_cast<float4*>(&g_P[agg]) = make_float4(P0, P1, P2, P3);
    *reinterpret_cast<float4*>(&g_Q[agg]) = make_float4(Q0, Q1, Q2, Q3);
}

// ============================================================================
// Pass B1: group aggregates (parallel). One CTA per (batch, group).
// Register-prefetch all loads, then run the pure-FMA chains.
// ============================================================================
__global__ void __launch_bounds__(128)
passB1_kernel() {
    const int b = blockIdx.x >> 5;        // / NG
    const int g = blockIdx.x & (NG - 1);
    const int d = threadIdx.x;

    // ---- vector group aggregate: prefetch GC (P,Q) pairs, then chain ----
    float Pr[GC], Qr[GC];
#pragma unroll
    for (int kk = 0; kk < GC; ++kk) {
        const int idx = (b * NCn + g * GC + kk) * Dn + d;
        Pr[kk] = g_P[idx];
        Qr[kk] = g_Q[idx];
    }
    float P = Pr[0], Q = Qr[0];
#pragma unroll
    for (int kk = 1; kk < GC; ++kk) {
        Q = fmaf(Pr[kk], Q, Qr[kk]);
        P *= Pr[kk];
    }
    g_GP[(b * NG + g) * Dn + d] = P;
    g_GQ[(b * NG + g) * Dn + d] = Q;

    // ---- scalar group scan (warp 0): LPL per lane + shfl affine scan ----
    if (threadIdx.x < 32) {
        const int lane = threadIdx.x;
        const int tb = b * Sn + g * TG + lane * LPL;
        float mr[LPL], sr[LPL];
#pragma unroll
        for (int i = 0; i < LPL; ++i) { mr[i] = g_m[tb + i]; sr[i] = g_s[tb + i]; }
        float M = mr[0], S = sr[0];
#pragma unroll
        for (int i = 1; i < LPL; ++i) { S = fmaf(mr[i], S, sr[i]); M *= mr[i]; }
#pragma unroll
        for (int off = 1; off < 32; off <<= 1) {
            const float Mp = __shfl_up_sync(0xffffffffu, M, off);
            const float Sp = __shfl_up_sync(0xffffffffu, S, off);
            if (lane >= off) { S = fmaf(M, Sp, S); M = M * Mp; }
        }
        float Mex = __shfl_up_sync(0xffffffffu, M, 1);
        float Sex = __shfl_up_sync(0xffffffffu, S, 1);
        if (lane == 0) { Mex = 1.f; Sex = 0.f; }
        g_laneM[(b * NG + g) * 32 + lane] = Mex;
        g_laneS[(b * NG + g) * 32 + lane] = Sex;
        if (lane == 31) {
            g_GAM[b * NG + g] = M;
            g_GAS[b * NG + g] = S;
        }
    }
}

// ============================================================================
// Pass B3: distribute prefixes down (parallel). One CTA per (batch, group).
// Each CTA computes its OWN group-exclusive prefix from the group aggregates
// (redundant across CTAs but fully parallel).
// ============================================================================
__global__ void __launch_bounds__(128)
passB3_kernel() {
    const int b = blockIdx.x >> 5;
    const int g = blockIdx.x & (NG - 1);
    const int d = threadIdx.x;

    // group-exclusive vector prefix for this batch/channel
    float b0 = 0.f;
    {
        float GPr[NG], GQr[NG];
#pragma unroll
        for (int gg = 0; gg < NG; ++gg) {
            const int idx = (b * NG + gg) * Dn + d;
            GPr[gg] = g_GP[idx];
            GQr[gg] = g_GQ[idx];
        }
#pragma unroll
        for (int gg = 0; gg < NG; ++gg) {
            if (gg < g) b0 = fmaf(GPr[gg], b0, GQr[gg]);
        }
    }

    // ---- vector rescan: prefetch, then chain + stores ----
    {
        float Pr[GC], Qr[GC];
#pragma unroll
        for (int kk = 0; kk < GC; ++kk) {
            const int idx = (b * NCn + g * GC + kk) * Dn + d;
            Pr[kk] = g_P[idx];
            Qr[kk] = g_Q[idx];
        }
#pragma unroll
        for (int kk = 0; kk < GC; ++kk) {
            g_b0[(b * NCn + g * GC + kk) * Dn + d] = b0;
            b0 = fmaf(Pr[kk], b0, Qr[kk]);
        }
    }

    // ---- scalar rescan: write rinv for all TG timesteps ----
    if (threadIdx.x < 32) {
        const int lane = threadIdx.x;
        // group-exclusive scalar prefix via shfl scan over group aggregates
        float M = g_GAM[b * NG + lane];
        float S = g_GAS[b * NG + lane];
#pragma unroll
        for (int off = 1; off < 32; off <<= 1) {
            const float Mp = __shfl_up_sync(0xffffffffu, M, off);
            const float Sp = __shfl_up_sync(0xffffffffu, S, off);
            if (lane >= off) { S = fmaf(M, Sp, S); M = M * Mp; }
        }
        // a0 for group g = inclusive S at lane g-1 (a starts at 0)
        const float Sincl = S;
        const float a0g = (g == 0) ? 0.f
                        : __shfl_sync(0xffffffffu, Sincl, g - 1);

        const float Mex = g_laneM[(b * NG + g) * 32 + lane];
        const float Sex = g_laneS[(b * NG + g) * 32 + lane];
        const int tb = b * Sn + g * TG + lane * LPL;
        float mr[LPL], sr[LPL];
#pragma unroll
        for (int i = 0; i < LPL; ++i) { mr[i] = g_m[tb + i]; sr[i] = g_s[tb + i]; }
        float a = fmaf(Mex, a0g, Sex);
#pragma unroll
        for (int i = 0; i < LPL; ++i) {
            a = fmaf(mr[i], a, sr[i]);
            g_rinv[tb + i] = __fdividef(1.0f, a + 1e-8f);
        }
    }
}

// ============================================================================
// Pass C: replay each chunk from its start state, emit LayerNorm'd output.
// One warp per (batch, chunk); lane owns 4 channels. rinv precomputed.
// Inputs read with evict_first (last use); output streamed past L2.
// ============================================================================
__global__ void __launch_bounds__(256)
passC_kernel(const float* __restrict__ C, const float* __restrict__ V,
             const float* __restrict__ W, const float* __restrict__ enc,
             const float* __restrict__ tmod, const float* __restrict__ cmod,
             const float* __restrict__ lnw, const float* __restrict__ lnb,
             float* __restrict__ out) {
    const int warp = (blockIdx.x * blockDim.x + threadIdx.x) >> 5;
    const int lane = threadIdx.x & 31;
    const int b = warp >> 9;
    const int k = warp & (NCn - 1);
    const int t0 = k * Ln;
    const int d4 = lane * 4;

    const uint64_t pol = pol_evict_first();

    float rv = 0.f;
    if (lane < Ln) rv = g_rinv[b * Sn + t0 + lane];

    const float4 tm = *reinterpret_cast<const float4*>(tmod + d4);
    const float4 cm = *reinterpret_cast<const float4*>(cmod + d4);
    const float4 eb = *reinterpret_cast<const float4*>(enc + b * Dn + d4);
    const float ctx0 = fsig(eb.x * cm.x) * eb.x;
    const float ctx1 = fsig(eb.y * cm.y) * eb.y;
    const float ctx2 = fsig(eb.z * cm.z) * eb.z;
    const float ctx3 = fsig(eb.w * cm.w) * eb.w;
    const float4 w4 = *reinterpret_cast<const float4*>(lnw + d4);
    const float4 b4 = *reinterpret_cast<const float4*>(lnb + d4);

    float4 bst = *reinterpret_cast<const float4*>(&g_b0[(b * NCn + k) * Dn + d4]);

    const size_t base = ((size_t)b * Sn + t0) * Dn + d4;
    const float4* pC = reinterpret_cast<const float4*>(C + base);
    const float4* pV = reinterpret_cast<const float4*>(V + base);
    const float4* pW = reinterpret_cast<const float4*>(W + base);
    float4* pO = reinterpret_cast<float4*>(out + base);

#pragma unroll
    for (int t = 0; t < Ln; ++t) {
        const float4 c = ldg_pol(pC + t * (Dn / 4), pol);
        const float4 v = ldg_pol(pV + t * (Dn / 4), pol);
        const float4 w = ldg_pol(pW + t * (Dn / 4), pol);

        const float dd0 = fsig(w.x * tm.x), dd1 = fsig(w.y * tm.y);
        const float dd2 = fsig(w.z * tm.z), dd3 = fsig(w.w * tm.w);
        const float e0 = __expf(c.x), e1 = __expf(c.y);
        const float e2 = __expf(c.z), e3 = __expf(c.w);

        bst.x = fmaf(dd0, bst.x, fmaf(e0, v.x, ctx0));
        bst.y = fmaf(dd1, bst.y, fmaf(e1, v.y, ctx1));
        bst.z = fmaf(dd2, bst.z, fmaf(e2, v.z, ctx2));
        bst.w = fmaf(dd3, bst.w, fmaf(e3, v.w, ctx3));

        const float rinv = __shfl_sync(0xffffffffu, rv, t);
        const float o0 = bst.x * rinv, o1 = bst.y * rinv;
        const float o2 = bst.z * rinv, o3 = bst.w * rinv;

        float lsum = (o0 + o1) + (o2 + o3);
        float lsq  = fmaf(o0, o0, fmaf(o1, o1, fmaf(o2, o2, o3 * o3)));
        warp_allreduce2(lsum, lsq);
        const float mu  = lsum * (1.0f / (float)Dn);
        const float var = fmaf(-mu, mu, lsq * (1.0f / (float)Dn));
        const float rstd = rsqrtf(var + 1e-5f);

        float4 r;
        r.x = fmaf((o0 - mu) * rstd, w4.x, b4.x);
        r.y = fmaf((o1 - mu) * rstd, w4.y, b4.y);
        r.z = fmaf((o2 - mu) * rstd, w4.z, b4.z);
        r.w = fmaf((o3 - mu) * rstd, w4.w, b4.w);
        stg_stream(pO + t * (Dn / 4), r);
    }
}

// ============================================================================
extern "C" void kernel_launch(void* const* d_in, const int* in_sizes, int n_in,
                              void* d_out, int out_size) {
    (void)in_sizes; (void)n_in; (void)out_size;
    const float* C    = (const float*)d_in[0];
    const float* V    = (const float*)d_in[1];
    const float* W    = (const float*)d_in[2];
    const float* enc  = (const float*)d_in[3];
    const float* tmod = (const float*)d_in[4];
    const float* cmod = (const float*)d_in[5];
    const float* lnw  = (const float*)d_in[6];
    const float* lnb  = (const float*)d_in[7];
    float* out = (float*)d_out;

    const int warpsTotal = Bn * NCn;            // 8192
    const int blocks = warpsTotal / 8;          // 1024 blocks of 256 threads

    passA_kernel<<<blocks, 256>>>(C, V, W, enc, tmod, cmod);
    passB1_kernel<<<Bn * NG, 128>>>();
    passB3_kernel<<<Bn * NG, 128>>>();
    passC_kernel<<<blocks, 256>>>(C, V, W, enc, tmod, cmod, lnw, lnb, out);
}